// round 9
// baseline (speedup 1.0000x reference)
#include <cuda_runtime.h>
#include <cuda_bf16.h>
#include <stdint.h>
#include <string.h>

// ---------------- problem shape (fixed) ----------------
#define T_TOK 16384
#define D_HID 4096
#define E_EXP 256
#define TOPK  8

#define BM 32
#define BN 128
#define NKC (D_HID / 16)        // 256 k16 chunks
#define PRE 5                   // pipeline stages

#define A_PITCH 80              // 64B data + 16B pad
#define A_STG (BM * A_PITCH)    // 2560
#define B_STG 8192              // 512 x uint4 (128 experts * 4 lanegroups)
#define STG   (A_STG + B_STG)   // 10752
#define SMEM_TOTAL (PRE * STG)  // 53760 -> 4 CTAs/SM = 215KB

#define N_MTILE (T_TOK / BM)    // 512

// W packed fragment-order: idx = kc*1024 + n*4 + l4
// uint4 = { hi(k0,k1), hi(k8,k9), lo(k0,k1), lo(k8,k9) }, k = kc*16 + l4*2 (+8)
__device__ uint4 g_Wp[NKC * E_EXP * 4];
__device__ unsigned g_sync[N_MTILE];

// ---------------- helpers ----------------
__device__ __forceinline__ uint32_t smem_u32(const void* p) {
    uint32_t a;
    asm("{ .reg .u64 t; cvta.to.shared.u64 t, %1; cvt.u32.u64 %0, t; }" : "=r"(a) : "l"(p));
    return a;
}
__device__ __forceinline__ void cp16(void* dst_smem, const void* src_gmem) {
    uint32_t d = smem_u32(dst_smem);
    asm volatile("cp.async.cg.shared.global [%0], [%1], 16;" :: "r"(d), "l"(src_gmem) : "memory");
}
#define CP_COMMIT()  asm volatile("cp.async.commit_group;" ::: "memory")
#define CP_WAIT3()   asm volatile("cp.async.wait_group 3;" ::: "memory")

__device__ __forceinline__ void mma16816(float* c, const uint32_t* a, uint32_t b0, uint32_t b1) {
    asm volatile(
        "mma.sync.aligned.m16n8k16.row.col.f32.bf16.bf16.f32 "
        "{%0,%1,%2,%3}, {%4,%5,%6,%7}, {%8,%9}, {%0,%1,%2,%3};"
        : "+f"(c[0]), "+f"(c[1]), "+f"(c[2]), "+f"(c[3])
        : "r"(a[0]), "r"(a[1]), "r"(a[2]), "r"(a[3]), "r"(b0), "r"(b1));
}

__device__ __forceinline__ void split2(float f0, float f1, uint32_t& h, uint32_t& l) {
    __nv_bfloat162 hb = __floats2bfloat162_rn(f0, f1);
    uint32_t hu; memcpy(&hu, &hb, 4);
    float g0 = __uint_as_float(hu << 16);
    float g1 = __uint_as_float(hu & 0xffff0000u);
    __nv_bfloat162 lb = __floats2bfloat162_rn(f0 - g0, f1 - g1);
    uint32_t lu; memcpy(&lu, &lb, 4);
    h = hu; l = lu;
}

// ---------------- router body: identical numerics to standalone ------------
__device__ __forceinline__ void route_token(
    int t, int lane,
    const float* __restrict__ score, const float* __restrict__ bias,
    float* __restrict__ outW, float* __restrict__ outI)
{
    float v[8], bj[8];
    #pragma unroll
    for (int j = 0; j < 8; ++j) {
        v[j]  = score[(size_t)t * E_EXP + lane + 32 * j];
        bj[j] = bias[lane + 32 * j];
    }
    float m = v[0];
    #pragma unroll
    for (int j = 1; j < 8; ++j) m = fmaxf(m, v[j]);
    #pragma unroll
    for (int o = 16; o > 0; o >>= 1) m = fmaxf(m, __shfl_xor_sync(0xFFFFFFFFu, m, o));
    float p[8], s = 0.f;
    #pragma unroll
    for (int j = 0; j < 8; ++j) { p[j] = expf(v[j] - m); s += p[j]; }
    #pragma unroll
    for (int o = 16; o > 0; o >>= 1) s += __shfl_xor_sync(0xFFFFFFFFu, s, o);
    float sc[8], biased[8];
    #pragma unroll
    for (int j = 0; j < 8; ++j) { sc[j] = p[j] / s; biased[j] = sc[j] + bj[j]; }

    unsigned picked = 0;
    #pragma unroll
    for (int rnk = 0; rnk < TOPK; ++rnk) {
        float bv = -__int_as_float(0x7f800000);
        int   bi = 0x7fffffff;
        float bu = 0.f;
        #pragma unroll
        for (int j = 0; j < 8; ++j) {
            if (!((picked >> j) & 1u)) {
                int idx = lane + 32 * j;
                float cv = biased[j];
                if (cv > bv || (cv == bv && idx < bi)) { bv = cv; bi = idx; bu = sc[j]; }
            }
        }
        #pragma unroll
        for (int o = 16; o > 0; o >>= 1) {
            float ov = __shfl_xor_sync(0xFFFFFFFFu, bv, o);
            int   oi = __shfl_xor_sync(0xFFFFFFFFu, bi, o);
            float ou = __shfl_xor_sync(0xFFFFFFFFu, bu, o);
            if (ov > bv || (ov == bv && oi < bi)) { bv = ov; bi = oi; bu = ou; }
        }
        if (lane == (bi & 31)) picked |= 1u << (bi >> 5);
        if (lane == rnk) {
            outW[(size_t)t * TOPK + rnk] = bu * 1.5f;
            outI[(size_t)t * TOPK + rnk] = (float)bi;
        }
    }
}

// ---------------- kernel 1: pack W into fragment order (hi/lo) -------------
__global__ void cvt_w_kernel(const float* __restrict__ W) {
    int t = blockIdx.x * blockDim.x + threadIdx.x;   // 0 .. NKC*256*4-1
    if (t < N_MTILE) g_sync[t] = 0;                  // reset ALL fusion flags
    int l4 = t & 3;
    int n  = (t >> 2) & 255;
    int kc = t >> 10;
    const float* p = W + (size_t)n * D_HID + kc * 16 + l4 * 2;
    float2 x = *(const float2*)p;          // k0, k1
    float2 y = *(const float2*)(p + 8);    // k8, k9
    uint4 o;
    split2(x.x, x.y, o.x, o.z);
    split2(y.x, y.y, o.y, o.w);
    g_Wp[t] = o;
}

// ---------------- kernel 2: HMMA bf16x3 GEMM, 32x128 CTA + fused router ----
__global__ void __launch_bounds__(128, 4)
gemm_kernel(const float* __restrict__ A, float* __restrict__ outS,
            const float* __restrict__ bias,
            float* __restrict__ outW, float* __restrict__ outI) {
    extern __shared__ char smem[];
    const int tid  = threadIdx.x;
    const int lane = tid & 31;
    const int warp = tid >> 5;           // 0..3
    const int wm   = warp >> 1;          // 0..1  (rows wm*16)
    const int wn   = warp & 1;           // 0..1  (cols wn*64)
    const int m0   = blockIdx.y * BM;    // n-tile fastest -> A L2 reuse
    const int n0   = blockIdx.x * BN;
    const int r    = lane >> 2;          // 0..7
    const int t4   = lane & 3;           // 0..3
    const int c2   = t4 * 2;             // 0,2,4,6

    // cp.async A: 32 rows * 4 segs = 128 copies, one per thread
    const int a_row = tid >> 2, a_seg = tid & 3;
    const float* gA = A + (size_t)(m0 + a_row) * D_HID + a_seg * 4;
    char* aDst = smem + a_row * A_PITCH + a_seg * 16;
    // cp.async B: 512 uint4/stage; thread copies elems tid, tid+128, +256, +384
    const uint4* gB = g_Wp + (size_t)n0 * 4 + tid;
    char* bDst = smem + A_STG + tid * 16;

    // LDS bases
    char* aLds = smem + (wm * 16 + r) * A_PITCH + c2 * 4;
    char* bLds = smem + A_STG + ((size_t)(wn * 64 + r) * 4 + t4) * 16;

    float acc[8][4];
    #pragma unroll
    for (int f = 0; f < 8; ++f)
        #pragma unroll
        for (int q = 0; q < 4; ++q) acc[f][q] = 0.f;

    // prologue: stages 0..PRE-2
    #pragma unroll
    for (int s = 0; s < PRE - 1; ++s) {
        size_t so = (size_t)s * STG;
        cp16(aDst + so, gA + s * 16);
        #pragma unroll
        for (int j = 0; j < 4; ++j)
            cp16(bDst + so + j * 2048, gB + (size_t)s * 1024 + j * 128);
        CP_COMMIT();
    }

    for (int kc = 0; kc < NKC; ++kc) {
        CP_WAIT3();
        __syncthreads();

        int kn = kc + PRE - 1;
        if (kn < NKC) {
            size_t so = (size_t)(kn % PRE) * STG;
            cp16(aDst + so, gA + kn * 16);
            #pragma unroll
            for (int j = 0; j < 4; ++j)
                cp16(bDst + so + j * 2048, gB + (size_t)kn * 1024 + j * 128);
        }
        CP_COMMIT();   // exactly one group per iteration

        size_t so = (size_t)(kc % PRE) * STG;

        // A fragment (f32 from smem), split into bf16 hi/lo
        const char* ab = aLds + so;
        float2 f01 = *(const float2*)(ab);
        float2 f23 = *(const float2*)(ab + 8 * A_PITCH);
        float2 f45 = *(const float2*)(ab + 32);
        float2 f67 = *(const float2*)(ab + 8 * A_PITCH + 32);
        uint32_t ah[4], al[4];
        split2(f01.x, f01.y, ah[0], al[0]);
        split2(f23.x, f23.y, ah[1], al[1]);
        split2(f45.x, f45.y, ah[2], al[2]);
        split2(f67.x, f67.y, ah[3], al[3]);

        // B in groups of 4 n-frags to bound live registers
        #pragma unroll
        for (int g = 0; g < 2; ++g) {
            uint4 b[4];
            #pragma unroll
            for (int j = 0; j < 4; ++j)
                b[j] = *(const uint4*)(bLds + so + (size_t)(g * 4 + j) * 512);
            #pragma unroll
            for (int j = 0; j < 4; ++j)
                mma16816(acc[g * 4 + j], ah, b[j].x, b[j].y);   // Ahi*Bhi
            #pragma unroll
            for (int j = 0; j < 4; ++j)
                mma16816(acc[g * 4 + j], ah, b[j].z, b[j].w);   // Ahi*Blo
            #pragma unroll
            for (int j = 0; j < 4; ++j)
                mma16816(acc[g * 4 + j], al, b[j].x, b[j].y);   // Alo*Bhi
        }
    }

    // epilogue: warp writes 16x64
    int row0 = m0 + wm * 16 + r;
    float* po = outS + (size_t)row0 * E_EXP + n0 + wn * 64 + c2;
    #pragma unroll
    for (int f = 0; f < 8; ++f) {
        *(float2*)(po + f * 8)             = make_float2(acc[f][0], acc[f][1]);
        *(float2*)(po + 8 * E_EXP + f * 8) = make_float2(acc[f][2], acc[f][3]);
    }

    // ---- fused router: second CTA to finish this m-tile routes its 32 tokens
    __threadfence();
    __syncthreads();
    if (tid == 0)
        ((unsigned*)smem)[0] = atomicAdd(&g_sync[blockIdx.y], 1u);
    __syncthreads();
    if (((unsigned*)smem)[0] == 1u) {
        __threadfence();   // acquire partner CTA's score writes
        #pragma unroll
        for (int i = 0; i < 8; ++i)
            route_token(m0 + warp * 8 + i, lane, outS, bias, outW, outI);
        __syncthreads();
        if (tid == 0) g_sync[blockIdx.y] = 0;   // self-clean for next call
    }
}

// ---------------- launch ----------------
extern "C" void kernel_launch(void* const* d_in, const int* in_sizes, int n_in,
                              void* d_out, int out_size) {
    (void)n_in; (void)in_sizes; (void)out_size;
    const float* A    = (const float*)d_in[0];
    const float* W    = (const float*)d_in[1];
    const float* bias = (const float*)d_in[2];
    float* out  = (float*)d_out;
    float* outS = out;
    float* outW = out + (size_t)T_TOK * E_EXP;
    float* outI = outW + (size_t)T_TOK * TOPK;

    cudaFuncSetAttribute(gemm_kernel, cudaFuncAttributeMaxDynamicSharedMemorySize, SMEM_TOTAL);

    cvt_w_kernel<<<(NKC * E_EXP * 4) / 256, 256>>>(W);
    dim3 grid(E_EXP / BN, T_TOK / BM);   // n fastest -> A reuse in L2
    gemm_kernel<<<grid, 128, SMEM_TOTAL>>>(A, outS, bias, outW, outI);
}

// round 10
// speedup vs baseline: 1.3287x; 1.3287x over previous
#include <cuda_runtime.h>
#include <cuda_bf16.h>
#include <stdint.h>
#include <string.h>

// ---------------- problem shape (fixed) ----------------
#define T_TOK 16384
#define D_HID 4096
#define E_EXP 256
#define TOPK  8

#define BM 32
#define BN 128
#define NKC (D_HID / 16)        // 256 k16 chunks
#define PRE 4                   // pipeline stages (power of 2)

#define A_PITCH 80              // 64B data + 16B pad
#define A_STG (BM * A_PITCH)    // 2560
#define B_STG 8192              // 512 x uint4 (128 experts * 4 lanegroups)
#define STG   (A_STG + B_STG)   // 10752
#define SMEM_TOTAL (PRE * STG)  // 43008 -> 5 CTAs/SM = 215KB

// W packed fragment-order: idx = kc*1024 + n*4 + l4
// uint4 = { hi(k0,k1), hi(k8,k9), lo(k0,k1), lo(k8,k9) }, k = kc*16 + l4*2 (+8)
__device__ uint4 g_Wp[NKC * E_EXP * 4];

// ---------------- helpers ----------------
__device__ __forceinline__ uint32_t smem_u32(const void* p) {
    uint32_t a;
    asm("{ .reg .u64 t; cvta.to.shared.u64 t, %1; cvt.u32.u64 %0, t; }" : "=r"(a) : "l"(p));
    return a;
}
__device__ __forceinline__ void cp16(void* dst_smem, const void* src_gmem) {
    uint32_t d = smem_u32(dst_smem);
    asm volatile("cp.async.cg.shared.global [%0], [%1], 16;" :: "r"(d), "l"(src_gmem) : "memory");
}
#define CP_COMMIT()  asm volatile("cp.async.commit_group;" ::: "memory")
#define CP_WAIT2()   asm volatile("cp.async.wait_group 2;" ::: "memory")

__device__ __forceinline__ void mma16816(float* c, const uint32_t* a, uint32_t b0, uint32_t b1) {
    asm volatile(
        "mma.sync.aligned.m16n8k16.row.col.f32.bf16.bf16.f32 "
        "{%0,%1,%2,%3}, {%4,%5,%6,%7}, {%8,%9}, {%0,%1,%2,%3};"
        : "+f"(c[0]), "+f"(c[1]), "+f"(c[2]), "+f"(c[3])
        : "r"(a[0]), "r"(a[1]), "r"(a[2]), "r"(a[3]), "r"(b0), "r"(b1));
}

__device__ __forceinline__ void split2(float f0, float f1, uint32_t& h, uint32_t& l) {
    __nv_bfloat162 hb = __floats2bfloat162_rn(f0, f1);
    uint32_t hu; memcpy(&hu, &hb, 4);
    float g0 = __uint_as_float(hu << 16);
    float g1 = __uint_as_float(hu & 0xffff0000u);
    __nv_bfloat162 lb = __floats2bfloat162_rn(f0 - g0, f1 - g1);
    uint32_t lu; memcpy(&lu, &lb, 4);
    h = hu; l = lu;
}

// ---------------- kernel 1: pack W into fragment order (hi/lo) -------------
__global__ void cvt_w_kernel(const float* __restrict__ W) {
    int t = blockIdx.x * blockDim.x + threadIdx.x;   // 0 .. NKC*256*4-1
    int l4 = t & 3;
    int n  = (t >> 2) & 255;
    int kc = t >> 10;
    const float* p = W + (size_t)n * D_HID + kc * 16 + l4 * 2;
    float2 x = *(const float2*)p;          // k0, k1
    float2 y = *(const float2*)(p + 8);    // k8, k9
    uint4 o;
    split2(x.x, x.y, o.x, o.z);
    split2(y.x, y.y, o.y, o.w);
    g_Wp[t] = o;
}

// ---------------- kernel 2: HMMA bf16x3 GEMM, 32x128 CTA, 5 CTA/SM ---------
__global__ void __launch_bounds__(128, 5)
gemm_kernel(const float* __restrict__ A, float* __restrict__ outS) {
    extern __shared__ char smem[];
    const int tid  = threadIdx.x;
    const int lane = tid & 31;
    const int warp = tid >> 5;           // 0..3
    const int wm   = warp >> 1;          // 0..1  (rows wm*16)
    const int wn   = warp & 1;           // 0..1  (cols wn*64)
    const int m0   = blockIdx.y * BM;    // n-tile fastest -> A L2 reuse
    const int n0   = blockIdx.x * BN;
    const int r    = lane >> 2;          // 0..7
    const int t4   = lane & 3;           // 0..3
    const int c2   = t4 * 2;             // 0,2,4,6

    // cp.async A: 32 rows * 4 segs = 128 copies, one per thread
    const int a_row = tid >> 2, a_seg = tid & 3;
    const float* gA = A + (size_t)(m0 + a_row) * D_HID + a_seg * 4;
    char* aDst = smem + a_row * A_PITCH + a_seg * 16;
    // cp.async B: 512 uint4/stage; thread copies elems tid, tid+128, +256, +384
    const uint4* gB = g_Wp + (size_t)n0 * 4 + tid;
    char* bDst = smem + A_STG + tid * 16;

    // LDS bases (32-bit offsets only in the hot loop)
    char* aLds = smem + (wm * 16 + r) * A_PITCH + c2 * 4;
    char* bLds = smem + A_STG + ((wn * 64 + r) * 4 + t4) * 16;

    float acc[8][4];
    #pragma unroll
    for (int f = 0; f < 8; ++f)
        #pragma unroll
        for (int q = 0; q < 4; ++q) acc[f][q] = 0.f;

    // prologue: stages 0..PRE-2 (3 commits)
    #pragma unroll
    for (int s = 0; s < PRE - 1; ++s) {
        int so = s * STG;
        cp16(aDst + so, gA + s * 16);
        #pragma unroll
        for (int j = 0; j < 4; ++j)
            cp16(bDst + so + j * 2048, gB + (size_t)s * 1024 + j * 128);
        CP_COMMIT();
    }

    for (int kc = 0; kc < NKC; ++kc) {
        CP_WAIT2();
        __syncthreads();

        int kn = kc + PRE - 1;
        if (kn < NKC) {
            int so = (kn & (PRE - 1)) * STG;
            cp16(aDst + so, gA + kn * 16);
            #pragma unroll
            for (int j = 0; j < 4; ++j)
                cp16(bDst + so + j * 2048, gB + (size_t)kn * 1024 + j * 128);
        }
        CP_COMMIT();   // exactly one group per iteration

        const int so = (kc & (PRE - 1)) * STG;

        // A fragment (f32 from smem), split into bf16 hi/lo
        const char* ab = aLds + so;
        float2 f01 = *(const float2*)(ab);
        float2 f23 = *(const float2*)(ab + 8 * A_PITCH);
        float2 f45 = *(const float2*)(ab + 32);
        float2 f67 = *(const float2*)(ab + 8 * A_PITCH + 32);
        uint32_t ah[4], al[4];
        split2(f01.x, f01.y, ah[0], al[0]);
        split2(f23.x, f23.y, ah[1], al[1]);
        split2(f45.x, f45.y, ah[2], al[2]);
        split2(f67.x, f67.y, ah[3], al[3]);

        // B in groups of 4 n-frags to bound live registers
        #pragma unroll
        for (int g = 0; g < 2; ++g) {
            uint4 b[4];
            #pragma unroll
            for (int j = 0; j < 4; ++j)
                b[j] = *(const uint4*)(bLds + so + (g * 4 + j) * 512);
            #pragma unroll
            for (int j = 0; j < 4; ++j)
                mma16816(acc[g * 4 + j], ah, b[j].x, b[j].y);   // Ahi*Bhi
            #pragma unroll
            for (int j = 0; j < 4; ++j)
                mma16816(acc[g * 4 + j], ah, b[j].z, b[j].w);   // Ahi*Blo
            #pragma unroll
            for (int j = 0; j < 4; ++j)
                mma16816(acc[g * 4 + j], al, b[j].x, b[j].y);   // Alo*Bhi
        }
    }

    // epilogue: warp writes 16x64
    int row0 = m0 + wm * 16 + r;
    float* po = outS + (size_t)row0 * E_EXP + n0 + wn * 64 + c2;
    #pragma unroll
    for (int f = 0; f < 8; ++f) {
        *(float2*)(po + f * 8)             = make_float2(acc[f][0], acc[f][1]);
        *(float2*)(po + 8 * E_EXP + f * 8) = make_float2(acc[f][2], acc[f][3]);
    }
}

// ---------------- kernel 3: softmax + bias top-8 router (1 warp/token) -----
__global__ void __launch_bounds__(256, 8)
router_kernel(const float* __restrict__ score, const float* __restrict__ bias,
              float* __restrict__ outW, float* __restrict__ outI) {
    const int lane = threadIdx.x & 31;
    const int warp = threadIdx.x >> 5;
    const int t = blockIdx.x * 8 + warp;

    float v[8], bj[8];
    #pragma unroll
    for (int j = 0; j < 8; ++j) {
        v[j]  = score[(size_t)t * E_EXP + lane + 32 * j];
        bj[j] = bias[lane + 32 * j];
    }
    float m = v[0];
    #pragma unroll
    for (int j = 1; j < 8; ++j) m = fmaxf(m, v[j]);
    #pragma unroll
    for (int o = 16; o > 0; o >>= 1) m = fmaxf(m, __shfl_xor_sync(0xFFFFFFFFu, m, o));
    float p[8], s = 0.f;
    #pragma unroll
    for (int j = 0; j < 8; ++j) { p[j] = expf(v[j] - m); s += p[j]; }
    #pragma unroll
    for (int o = 16; o > 0; o >>= 1) s += __shfl_xor_sync(0xFFFFFFFFu, s, o);
    float sc[8], biased[8];
    #pragma unroll
    for (int j = 0; j < 8; ++j) { sc[j] = p[j] / s; biased[j] = sc[j] + bj[j]; }

    unsigned picked = 0;
    #pragma unroll
    for (int rnk = 0; rnk < TOPK; ++rnk) {
        float bv = -__int_as_float(0x7f800000);
        int   bi = 0x7fffffff;
        float bu = 0.f;
        #pragma unroll
        for (int j = 0; j < 8; ++j) {
            if (!((picked >> j) & 1u)) {
                int idx = lane + 32 * j;
                float cv = biased[j];
                if (cv > bv || (cv == bv && idx < bi)) { bv = cv; bi = idx; bu = sc[j]; }
            }
        }
        #pragma unroll
        for (int o = 16; o > 0; o >>= 1) {
            float ov = __shfl_xor_sync(0xFFFFFFFFu, bv, o);
            int   oi = __shfl_xor_sync(0xFFFFFFFFu, bi, o);
            float ou = __shfl_xor_sync(0xFFFFFFFFu, bu, o);
            if (ov > bv || (ov == bv && oi < bi)) { bv = ov; bi = oi; bu = ou; }
        }
        if (lane == (bi & 31)) picked |= 1u << (bi >> 5);
        if (lane == rnk) {
            outW[(size_t)t * TOPK + rnk] = bu * 1.5f;
            outI[(size_t)t * TOPK + rnk] = (float)bi;
        }
    }
}

// ---------------- launch ----------------
extern "C" void kernel_launch(void* const* d_in, const int* in_sizes, int n_in,
                              void* d_out, int out_size) {
    (void)n_in; (void)in_sizes; (void)out_size;
    const float* A    = (const float*)d_in[0];
    const float* W    = (const float*)d_in[1];
    const float* bias = (const float*)d_in[2];
    float* out  = (float*)d_out;
    float* outS = out;
    float* outW = out + (size_t)T_TOK * E_EXP;
    float* outI = outW + (size_t)T_TOK * TOPK;

    cudaFuncSetAttribute(gemm_kernel, cudaFuncAttributeMaxDynamicSharedMemorySize, SMEM_TOTAL);

    cvt_w_kernel<<<(NKC * E_EXP * 4) / 256, 256>>>(W);
    dim3 grid(E_EXP / BN, T_TOK / BM);   // n fastest -> A reuse in L2
    gemm_kernel<<<grid, 128, SMEM_TOTAL>>>(A, outS);
    router_kernel<<<T_TOK / 8, 256>>>(outS, bias, outW, outI);
}